// round 4
// baseline (speedup 1.0000x reference)
#include <cuda_runtime.h>
#include <cuda_bf16.h>
#include <cstdint>

#define B_ 64
#define N_ 2048
#define H_ 512
#define D_ 512
#define A_ 512
#define M_ (B_*N_)
#define NEG_INF_ -1.0e9f

// ---------------- persistent device scratch ----------------
__device__ float g_proj_h[B_*A_];
__device__ float g_scores[M_];
__device__ __align__(16) __nv_bfloat16 g_We_hi[A_*D_];
__device__ __align__(16) __nv_bfloat16 g_We_lo[A_*D_];
__device__ __align__(16) __nv_bfloat16 g_enc_hi[(size_t)M_*D_];   // 128 MB
__device__ __align__(16) __nv_bfloat16 g_enc_lo[(size_t)M_*D_];   // 128 MB

__device__ __forceinline__ uint32_t smem_u32(const void* p) {
    uint32_t a;
    asm("{ .reg .u64 t; cvta.to.shared.u64 t, %1; cvt.u32.u64 %0, t; }" : "=r"(a) : "l"(p));
    return a;
}

#define LDSM_X4(r, addr)                                                          \
    asm volatile("ldmatrix.sync.aligned.m8n8.x4.shared.b16 {%0,%1,%2,%3}, [%4];"  \
        : "=r"((r)[0]), "=r"((r)[1]), "=r"((r)[2]), "=r"((r)[3]) : "r"(addr))

#define MMA_BF16(d, a, b0, b1)                                                    \
    asm volatile("mma.sync.aligned.m16n8k16.row.col.f32.bf16.bf16.f32 "           \
        "{%0,%1,%2,%3}, {%4,%5,%6,%7}, {%8,%9}, {%0,%1,%2,%3};"                   \
        : "+f"((d)[0]), "+f"((d)[1]), "+f"((d)[2]), "+f"((d)[3])                  \
        : "r"((a)[0]), "r"((a)[1]), "r"((a)[2]), "r"((a)[3]), "r"(b0), "r"(b1))

#define CP16(dst, src)  asm volatile("cp.async.cg.shared.global [%0], [%1], 16;" :: "r"(dst), "l"(src))
#define CP_COMMIT()     asm volatile("cp.async.commit_group;" ::: "memory")
#define CP_WAIT1()      asm volatile("cp.async.wait_group 1;" ::: "memory")
#define CP_WAIT0()      asm volatile("cp.async.wait_group 0;" ::: "memory")

// smem: 3 stages of {EHI,ELO (128x32 bf16, 80B row stride), WHI,WLO (256x32)}
#define STG     61440
#define OFF_EHI 0
#define OFF_ELO 10240
#define OFF_WHI 20480
#define OFF_WLO 40960
#define OFF_VS  (3*STG)
#define OFF_PS  (OFF_VS + 2048)
#define OFF_RED (OFF_PS + 2048)
#define SMEM_BYTES (OFF_RED + 2048)

// ---------------------------------------------------------------------------
__global__ void proj_h_kernel(const float* __restrict__ h,
                              const float* __restrict__ Wh) {
    int gw   = blockIdx.x * 8 + (threadIdx.x >> 5);
    int lane = threadIdx.x & 31;
    int b = gw / A_, a = gw % A_;
    const float* hr = h  + (size_t)b * H_;
    const float* wr = Wh + (size_t)a * H_;
    float s = 0.f;
    #pragma unroll 4
    for (int k = lane; k < H_; k += 32) s += hr[k] * wr[k];
    #pragma unroll
    for (int o = 16; o > 0; o >>= 1) s += __shfl_xor_sync(0xffffffffu, s, o);
    if (lane == 0) g_proj_h[(size_t)b * A_ + a] = s;
}

__global__ void wsplit_kernel(const float* __restrict__ We) {
    int i = blockIdx.x * blockDim.x + threadIdx.x;
    float x = We[i];
    __nv_bfloat16 hh = __float2bfloat16(x);
    g_We_hi[i] = hh;
    g_We_lo[i] = __float2bfloat16(x - __bfloat162float(hh));
}

// split enc -> bf16 hi/lo (DRAM-bound one-shot)
__global__ void esplit_kernel(const float* __restrict__ enc) {
    size_t i = ((size_t)blockIdx.x * blockDim.x + threadIdx.x) * 4;
    float4 e = *(const float4*)(enc + i);
    __nv_bfloat16 hx = __float2bfloat16(e.x), hy = __float2bfloat16(e.y);
    __nv_bfloat16 hz = __float2bfloat16(e.z), hw = __float2bfloat16(e.w);
    uint32_t hi01 = (uint32_t)__bfloat16_as_ushort(hx) | ((uint32_t)__bfloat16_as_ushort(hy) << 16);
    uint32_t hi23 = (uint32_t)__bfloat16_as_ushort(hz) | ((uint32_t)__bfloat16_as_ushort(hw) << 16);
    float lx = e.x - __bfloat162float(hx), ly = e.y - __bfloat162float(hy);
    float lz = e.z - __bfloat162float(hz), lw = e.w - __bfloat162float(hw);
    uint32_t lo01, lo23;
    asm("cvt.rn.bf16x2.f32 %0, %1, %2;" : "=r"(lo01) : "f"(ly), "f"(lx));
    asm("cvt.rn.bf16x2.f32 %0, %1, %2;" : "=r"(lo23) : "f"(lw), "f"(lz));
    *(uint2*)(g_enc_hi + i) = make_uint2(hi01, hi23);
    *(uint2*)(g_enc_lo + i) = make_uint2(lo01, lo23);
}

// ---------------------------------------------------------------------------
// scores: 3-stage cp.async pipeline, bf16x3 HMMA, fused tanh/v epilogue.
// CTA: 128 M-rows; 32 chunk iters = 2 a-chunks x 16 K-chunks of 32.
// ---------------------------------------------------------------------------
__global__ __launch_bounds__(512, 1)
void scores_kernel(const float* __restrict__ v) {
    extern __shared__ char smem[];
    const uint32_t sb = smem_u32(smem);
    const int tid  = threadIdx.x;
    const int lane = tid & 31;
    const int w    = tid >> 5;
    const int wm   = w & 3;
    const int wn   = w >> 2;
    const int m0   = blockIdx.x * 128;
    const int b    = blockIdx.x >> 4;

    float* vs = (float*)(smem + OFF_VS);
    float* ps = (float*)(smem + OFF_PS);
    vs[tid] = v[tid];
    ps[tid] = g_proj_h[(size_t)b * A_ + tid];

    // per-thread cp.async coordinates
    const int rE   = tid >> 2;                 // 0..127
    const int sE   = tid & 3;                  // 16B segment
    const uint32_t dE = (uint32_t)rE * 80 + (uint32_t)sE * 16;
    const size_t   oE = (size_t)(m0 + rE) * D_ + sE * 8;
    const int rW0  = tid >> 2, rW1 = (tid + 512) >> 2;
    const uint32_t dW0 = (uint32_t)rW0 * 80 + (uint32_t)sE * 16;
    const uint32_t dW1 = (uint32_t)rW1 * 80 + (uint32_t)sE * 16;

    // ldmatrix base addresses
    const uint32_t eOffHi = OFF_EHI + (uint32_t)(wm * 32 + (lane & 15)) * 80 + (uint32_t)(lane >> 4) * 16;
    const uint32_t eOffLo = eOffHi + (OFF_ELO - OFF_EHI);
    const int q = lane >> 3;
    const uint32_t wOffHi = OFF_WHI + (uint32_t)(wn * 64 + ((q >> 1) << 3) + (lane & 7)) * 80 + (uint32_t)(q & 1) * 16;
    const uint32_t wOffLo = wOffHi + (OFF_WLO - OFF_WHI);

    float c[2][8][4];
    float sp[4] = {0.f, 0.f, 0.f, 0.f};
    #pragma unroll
    for (int i = 0; i < 2; i++)
        #pragma unroll
        for (int j = 0; j < 8; j++)
            #pragma unroll
            for (int e = 0; e < 4; e++) c[i][j][e] = 0.f;

    // issue loads for chunk ci into stage ci%3
    auto issue = [&](int ci) {
        const int ac = ci >> 4;
        const int k0 = (ci & 15) * 32;
        const uint32_t base = sb + (uint32_t)(ci % 3) * STG;
        CP16(base + OFF_EHI + dE, (const char*)(g_enc_hi + oE + k0));
        CP16(base + OFF_ELO + dE, (const char*)(g_enc_lo + oE + k0));
        const size_t oW0 = (size_t)(ac * 256 + rW0) * D_ + sE * 8 + k0;
        const size_t oW1 = (size_t)(ac * 256 + rW1) * D_ + sE * 8 + k0;
        CP16(base + OFF_WHI + dW0, (const char*)(g_We_hi + oW0));
        CP16(base + OFF_WLO + dW0, (const char*)(g_We_lo + oW0));
        CP16(base + OFF_WHI + dW1, (const char*)(g_We_hi + oW1));
        CP16(base + OFF_WLO + dW1, (const char*)(g_We_lo + oW1));
    };

    issue(0); CP_COMMIT();
    issue(1); CP_COMMIT();

    #pragma unroll 1
    for (int ci = 0; ci < 32; ci++) {
        if (ci < 31) { CP_WAIT1(); } else { CP_WAIT0(); }
        __syncthreads();
        if (ci + 2 < 32) { issue(ci + 2); CP_COMMIT(); }

        const uint32_t stb = sb + (uint32_t)(ci % 3) * STG;
        #pragma unroll
        for (int s = 0; s < 2; s++) {
            uint32_t aHi[2][4], aLo[2][4];
            #pragma unroll
            for (int i = 0; i < 2; i++) {
                LDSM_X4(aHi[i], stb + eOffHi + (uint32_t)i * 1280 + (uint32_t)s * 32);
                LDSM_X4(aLo[i], stb + eOffLo + (uint32_t)i * 1280 + (uint32_t)s * 32);
            }
            #pragma unroll
            for (int g = 0; g < 4; g++) {
                uint32_t bH[4], bL[4];
                LDSM_X4(bH, stb + wOffHi + (uint32_t)g * 1280 + (uint32_t)s * 32);
                LDSM_X4(bL, stb + wOffLo + (uint32_t)g * 1280 + (uint32_t)s * 32);
                #pragma unroll
                for (int i = 0; i < 2; i++) {
                    MMA_BF16(c[i][2*g],   aHi[i], bH[0], bH[1]);
                    MMA_BF16(c[i][2*g+1], aHi[i], bH[2], bH[3]);
                    MMA_BF16(c[i][2*g],   aLo[i], bH[0], bH[1]);
                    MMA_BF16(c[i][2*g+1], aLo[i], bH[2], bH[3]);
                    MMA_BF16(c[i][2*g],   aHi[i], bL[0], bL[1]);
                    MMA_BF16(c[i][2*g+1], aHi[i], bL[2], bL[3]);
                }
            }
        }

        if ((ci & 15) == 15) {
            const int a0 = (ci >> 4) * 256;
            #pragma unroll
            for (int i = 0; i < 2; i++)
                #pragma unroll
                for (int j = 0; j < 8; j++)
                    #pragma unroll
                    for (int e = 0; e < 4; e++) {
                        int col = a0 + wn * 64 + j * 8 + (lane & 3) * 2 + (e & 1);
                        float x  = ps[col] + c[i][j][e];
                        float ex = __expf(2.f * x);
                        float th = 1.f - __fdividef(2.f, ex + 1.f);
                        sp[i * 2 + (e >> 1)] += vs[col] * th;
                        c[i][j][e] = 0.f;
                    }
        }
    }

    #pragma unroll
    for (int slot = 0; slot < 4; slot++) {
        sp[slot] += __shfl_xor_sync(0xffffffffu, sp[slot], 1);
        sp[slot] += __shfl_xor_sync(0xffffffffu, sp[slot], 2);
    }
    float* red = (float*)(smem + OFF_RED);
    __syncthreads();
    if ((lane & 3) == 0) {
        #pragma unroll
        for (int slot = 0; slot < 4; slot++) {
            int row = wm * 32 + (slot >> 1) * 16 + (slot & 1) * 8 + (lane >> 2);
            red[row * 4 + wn] = sp[slot];
        }
    }
    __syncthreads();
    if (tid < 128)
        g_scores[m0 + tid] = red[tid*4+0] + red[tid*4+1] + red[tid*4+2] + red[tid*4+3];
}

// ---------------------------------------------------------------------------
__global__ void softmax_kernel(const int* __restrict__ mask,
                               float* __restrict__ alpha) {
    __shared__ float sred[256];
    const int b   = blockIdx.x;
    const int tid = threadIdx.x;
    const float* sc = g_scores + (size_t)b * N_;
    const int*   mk = mask     + (size_t)b * N_;

    float vals[8];
    float mx = -3.4e38f;
    #pragma unroll
    for (int i = 0; i < 8; i++) {
        int n = tid + i * 256;
        float s = (mk[n] == 0) ? NEG_INF_ : sc[n];
        vals[i] = s;
        mx = fmaxf(mx, s);
    }
    sred[tid] = mx;
    __syncthreads();
    #pragma unroll
    for (int o = 128; o > 0; o >>= 1) {
        if (tid < o) sred[tid] = fmaxf(sred[tid], sred[tid + o]);
        __syncthreads();
    }
    mx = sred[0];
    __syncthreads();

    float sum = 0.f;
    #pragma unroll
    for (int i = 0; i < 8; i++) { vals[i] = expf(vals[i] - mx); sum += vals[i]; }
    sred[tid] = sum;
    __syncthreads();
    #pragma unroll
    for (int o = 128; o > 0; o >>= 1) {
        if (tid < o) sred[tid] += sred[tid + o];
        __syncthreads();
    }
    float inv = 1.f / sred[0];
    #pragma unroll
    for (int i = 0; i < 8; i++)
        alpha[(size_t)b * N_ + tid + i * 256] = vals[i] * inv;
}

// ---------------------------------------------------------------------------
__global__ void context_kernel(const float* __restrict__ enc,
                               const float* __restrict__ alpha,
                               float* __restrict__ ctx) {
    __shared__ float  sal[N_];
    __shared__ float4 sred[256];
    const int b  = blockIdx.x;
    const int d0 = blockIdx.y * 128;
    const int t  = threadIdx.x;
    for (int n = t; n < N_; n += 256) sal[n] = alpha[(size_t)b * N_ + n];
    __syncthreads();

    const int dl = (t & 31) * 4;
    const int nl = t >> 5;
    const float* base = enc + (size_t)b * N_ * D_ + d0 + dl;
    float4 acc = make_float4(0.f, 0.f, 0.f, 0.f);
    #pragma unroll 4
    for (int n = nl; n < N_; n += 8) {
        float a  = sal[n];
        float4 e = *(const float4*)(base + (size_t)n * D_);
        acc.x += a * e.x; acc.y += a * e.y; acc.z += a * e.z; acc.w += a * e.w;
    }
    sred[t] = acc;
    __syncthreads();
    if (t < 32) {
        float4 r = sred[t];
        #pragma unroll
        for (int j = 1; j < 8; j++) {
            float4 o = sred[t + 32 * j];
            r.x += o.x; r.y += o.y; r.z += o.z; r.w += o.w;
        }
        *(float4*)(ctx + (size_t)b * D_ + d0 + t * 4) = r;
    }
}

// ---------------------------------------------------------------------------
extern "C" void kernel_launch(void* const* d_in, const int* in_sizes, int n_in,
                              void* d_out, int out_size) {
    const float* h    = (const float*)d_in[0];
    const float* enc  = (const float*)d_in[1];
    const int*   mask = (const int*)  d_in[2];
    const float* Wh   = (const float*)d_in[3];
    const float* We   = (const float*)d_in[4];
    const float* v    = (const float*)d_in[5];

    float* out   = (float*)d_out;
    float* ctx   = out;               // (B, D) first
    float* alpha = out + B_ * D_;     // (B, N) second

    cudaFuncSetAttribute(scores_kernel, cudaFuncAttributeMaxDynamicSharedMemorySize, SMEM_BYTES);

    esplit_kernel <<<(M_ * (D_ / 4)) / 256, 256>>>(enc);
    proj_h_kernel <<<(B_ * A_) / 8, 256>>>(h, Wh);
    wsplit_kernel <<<512, 512>>>(We);
    scores_kernel <<<M_ / 128, 512, SMEM_BYTES>>>(v);
    softmax_kernel<<<B_, 256>>>(mask, alpha);
    context_kernel<<<dim3(B_, 4), 256>>>(enc, alpha, ctx);
}

// round 5
// speedup vs baseline: 1.6302x; 1.6302x over previous
#include <cuda_runtime.h>
#include <cuda_fp16.h>
#include <cstdint>

#define B_ 64
#define N_ 2048
#define H_ 512
#define D_ 512
#define A_ 512
#define M_ (B_*N_)
#define NEG_INF_ -1.0e9f

// ---------------- persistent device scratch ----------------
__device__ float g_proj_h[B_*A_];
__device__ float g_scores[M_];
__device__ __align__(16) __half g_We_hi[A_*D_];
__device__ __align__(16) __half g_We_lo[A_*D_];
__device__ __align__(16) __half g_enc_h[(size_t)M_*D_];   // 128 MB

__device__ __forceinline__ uint32_t smem_u32(const void* p) {
    uint32_t a;
    asm("{ .reg .u64 t; cvta.to.shared.u64 t, %1; cvt.u32.u64 %0, t; }" : "=r"(a) : "l"(p));
    return a;
}

#define LDSM_X4(r, addr)                                                          \
    asm volatile("ldmatrix.sync.aligned.m8n8.x4.shared.b16 {%0,%1,%2,%3}, [%4];"  \
        : "=r"((r)[0]), "=r"((r)[1]), "=r"((r)[2]), "=r"((r)[3]) : "r"(addr))

#define MMA_F16(d, a, b0, b1)                                                     \
    asm volatile("mma.sync.aligned.m16n8k16.row.col.f32.f16.f16.f32 "             \
        "{%0,%1,%2,%3}, {%4,%5,%6,%7}, {%8,%9}, {%0,%1,%2,%3};"                   \
        : "+f"((d)[0]), "+f"((d)[1]), "+f"((d)[2]), "+f"((d)[3])                  \
        : "r"((a)[0]), "r"((a)[1]), "r"((a)[2]), "r"((a)[3]), "r"(b0), "r"(b1))

#define CP16(dst, src)  asm volatile("cp.async.cg.shared.global [%0], [%1], 16;" :: "r"(dst), "l"(src))
#define CP_COMMIT()     asm volatile("cp.async.commit_group;" ::: "memory")
#define CP_WAIT0()      asm volatile("cp.async.wait_group 0;" ::: "memory")

// smem: 2 stages {E 128x64 fp16 (128B rows, SW128 xor), Whi/Wlo 256x64 fp16}
#define STG     81920
#define OFF_E   0
#define OFF_WH  16384
#define OFF_WL  49152
#define OFF_VS  (2*STG)
#define OFF_PS  (OFF_VS + 2048)
#define OFF_RED (OFF_PS + 2048)
#define SMEM_BYTES (OFF_RED + 2048)

// ---------------------------------------------------------------------------
__global__ void proj_h_kernel(const float* __restrict__ h,
                              const float* __restrict__ Wh) {
    int gw   = blockIdx.x * 8 + (threadIdx.x >> 5);
    int lane = threadIdx.x & 31;
    int b = gw / A_, a = gw % A_;
    const float* hr = h  + (size_t)b * H_;
    const float* wr = Wh + (size_t)a * H_;
    float s = 0.f;
    #pragma unroll 4
    for (int k = lane; k < H_; k += 32) s += hr[k] * wr[k];
    #pragma unroll
    for (int o = 16; o > 0; o >>= 1) s += __shfl_xor_sync(0xffffffffu, s, o);
    if (lane == 0) g_proj_h[(size_t)b * A_ + a] = s;
}

__global__ void wsplit_kernel(const float* __restrict__ We) {
    int i = blockIdx.x * blockDim.x + threadIdx.x;
    float x = We[i];
    __half hh = __float2half_rn(x);
    g_We_hi[i] = hh;
    g_We_lo[i] = __float2half_rn(x - __half2float(hh));
}

// enc -> fp16 (DRAM-bound one-shot: 256MB read, 128MB write)
__global__ void econv_kernel(const float* __restrict__ enc) {
    size_t i = ((size_t)blockIdx.x * blockDim.x + threadIdx.x) * 4;
    float4 e = *(const float4*)(enc + i);
    uint32_t p01, p23;
    asm("cvt.rn.f16x2.f32 %0, %1, %2;" : "=r"(p01) : "f"(e.y), "f"(e.x));
    asm("cvt.rn.f16x2.f32 %0, %1, %2;" : "=r"(p23) : "f"(e.w), "f"(e.z));
    *(uint2*)(g_enc_h + i) = make_uint2(p01, p23);
}

// ---------------------------------------------------------------------------
// scores: fp16 2-pass HMMA (enc fp16 x (W_hi + W_lo)), 2-stage cp.async,
// SW128-swizzled smem, K-chunks of 64, fused tanh/v epilogue.
// CTA: 128 M-rows; 16 iters = 2 a-chunks x 8 K-chunks.
// ---------------------------------------------------------------------------
__global__ __launch_bounds__(512, 1)
void scores_kernel(const float* __restrict__ v) {
    extern __shared__ char smem[];
    const uint32_t sb = smem_u32(smem);
    const int tid  = threadIdx.x;
    const int lane = tid & 31;
    const int w    = tid >> 5;
    const int wm   = w & 3;            // 32-row band
    const int wn   = w >> 2;           // 64-col band
    const int m0   = blockIdx.x * 128;
    const int b    = blockIdx.x >> 4;

    float* vs = (float*)(smem + OFF_VS);
    float* ps = (float*)(smem + OFF_PS);
    vs[tid] = v[tid];
    ps[tid] = g_proj_h[(size_t)b * A_ + tid];

    // ldmatrix lane geometry (SW128: within-row 16B segment XOR (row&7)*16)
    const uint32_t xr = (uint32_t)(lane & 7) * 16;
    const uint32_t eBase = OFF_E + (uint32_t)(wm * 32 + (lane & 15)) * 128;
    const uint32_t eT = (uint32_t)(lane >> 4) * 16;
    const int q = lane >> 3;
    const uint32_t wBase = (uint32_t)(wn * 64 + ((q >> 1) << 3) + (lane & 7)) * 128;
    const uint32_t wT = (uint32_t)(q & 1) * 16;

    float c[2][8][4];
    float sp[4] = {0.f, 0.f, 0.f, 0.f};
    #pragma unroll
    for (int i = 0; i < 2; i++)
        #pragma unroll
        for (int j = 0; j < 8; j++)
            #pragma unroll
            for (int e = 0; e < 4; e++) c[i][j][e] = 0.f;

    auto issue = [&](int ci) {
        const int ac = ci >> 3;
        const int k0 = (ci & 7) * 64;
        const uint32_t st = sb + (uint32_t)(ci & 1) * STG;
        #pragma unroll
        for (int i = 0; i < 2; i++) {                 // E: 1024 16B segs
            int idx = tid + i * 512, row = idx >> 3, seg = idx & 7;
            uint32_t sw = (uint32_t)row * 128 + (((uint32_t)seg * 16) ^ (((uint32_t)row & 7) * 16));
            CP16(st + OFF_E + sw, (const char*)(g_enc_h + (size_t)(m0 + row) * D_ + k0 + seg * 8));
        }
        #pragma unroll
        for (int i = 0; i < 4; i++) {                 // W hi/lo: 2048 segs each
            int idx = tid + i * 512, row = idx >> 3, seg = idx & 7;
            uint32_t sw = (uint32_t)row * 128 + (((uint32_t)seg * 16) ^ (((uint32_t)row & 7) * 16));
            size_t go = (size_t)(ac * 256 + row) * D_ + k0 + seg * 8;
            CP16(st + OFF_WH + sw, (const char*)(g_We_hi + go));
            CP16(st + OFF_WL + sw, (const char*)(g_We_lo + go));
        }
    };

    issue(0); CP_COMMIT();

    #pragma unroll 1
    for (int ci = 0; ci < 16; ci++) {
        CP_WAIT0();
        __syncthreads();
        if (ci + 1 < 16) { issue(ci + 1); CP_COMMIT(); }

        const uint32_t stb = sb + (uint32_t)(ci & 1) * STG;
        #pragma unroll
        for (int s = 0; s < 4; s++) {
            uint32_t aF[2][4];
            #pragma unroll
            for (int i = 0; i < 2; i++)
                LDSM_X4(aF[i], stb + eBase + (uint32_t)i * 2048 + (((uint32_t)s * 32 + eT) ^ xr));
            #pragma unroll
            for (int g = 0; g < 4; g++) {
                uint32_t bH[4], bL[4];
                uint32_t wo = wBase + (uint32_t)g * 2048 + (((uint32_t)s * 32 + wT) ^ xr);
                LDSM_X4(bH, stb + OFF_WH + wo);
                LDSM_X4(bL, stb + OFF_WL + wo);
                #pragma unroll
                for (int i = 0; i < 2; i++) {
                    MMA_F16(c[i][2*g],   aF[i], bH[0], bH[1]);
                    MMA_F16(c[i][2*g+1], aF[i], bH[2], bH[3]);
                    MMA_F16(c[i][2*g],   aF[i], bL[0], bL[1]);
                    MMA_F16(c[i][2*g+1], aF[i], bL[2], bL[3]);
                }
            }
        }

        if ((ci & 7) == 7) {        // end of a-chunk: fused tanh/v epilogue
            const int a0 = (ci >> 3) * 256;
            #pragma unroll
            for (int i = 0; i < 2; i++)
                #pragma unroll
                for (int j = 0; j < 8; j++)
                    #pragma unroll
                    for (int e = 0; e < 4; e++) {
                        int col = a0 + wn * 64 + j * 8 + (lane & 3) * 2 + (e & 1);
                        float x  = ps[col] + c[i][j][e];
                        float ex = __expf(2.f * x);
                        float th = 1.f - __fdividef(2.f, ex + 1.f);
                        sp[i * 2 + (e >> 1)] += vs[col] * th;
                        c[i][j][e] = 0.f;
                    }
        }
    }

    #pragma unroll
    for (int slot = 0; slot < 4; slot++) {
        sp[slot] += __shfl_xor_sync(0xffffffffu, sp[slot], 1);
        sp[slot] += __shfl_xor_sync(0xffffffffu, sp[slot], 2);
    }
    float* red = (float*)(smem + OFF_RED);
    __syncthreads();
    if ((lane & 3) == 0) {
        #pragma unroll
        for (int slot = 0; slot < 4; slot++) {
            int row = wm * 32 + (slot >> 1) * 16 + (slot & 1) * 8 + (lane >> 2);
            red[row * 4 + wn] = sp[slot];
        }
    }
    __syncthreads();
    if (tid < 128)
        g_scores[m0 + tid] = red[tid*4+0] + red[tid*4+1] + red[tid*4+2] + red[tid*4+3];
}

// ---------------------------------------------------------------------------
__global__ void softmax_kernel(const int* __restrict__ mask,
                               float* __restrict__ alpha) {
    __shared__ float sred[256];
    const int b   = blockIdx.x;
    const int tid = threadIdx.x;
    const float* sc = g_scores + (size_t)b * N_;
    const int*   mk = mask     + (size_t)b * N_;

    float vals[8];
    float mx = -3.4e38f;
    #pragma unroll
    for (int i = 0; i < 8; i++) {
        int n = tid + i * 256;
        float s = (mk[n] == 0) ? NEG_INF_ : sc[n];
        vals[i] = s;
        mx = fmaxf(mx, s);
    }
    sred[tid] = mx;
    __syncthreads();
    #pragma unroll
    for (int o = 128; o > 0; o >>= 1) {
        if (tid < o) sred[tid] = fmaxf(sred[tid], sred[tid + o]);
        __syncthreads();
    }
    mx = sred[0];
    __syncthreads();

    float sum = 0.f;
    #pragma unroll
    for (int i = 0; i < 8; i++) { vals[i] = expf(vals[i] - mx); sum += vals[i]; }
    sred[tid] = sum;
    __syncthreads();
    #pragma unroll
    for (int o = 128; o > 0; o >>= 1) {
        if (tid < o) sred[tid] += sred[tid + o];
        __syncthreads();
    }
    float inv = 1.f / sred[0];
    #pragma unroll
    for (int i = 0; i < 8; i++)
        alpha[(size_t)b * N_ + tid + i * 256] = vals[i] * inv;
}

// ---------------------------------------------------------------------------
// context[b,d] = sum_n alpha[b,n]*enc[b,n,d]; 512 thr, 4 indep streams (MLP 4)
// ---------------------------------------------------------------------------
__global__ __launch_bounds__(512)
void context_kernel(const float* __restrict__ enc,
                    const float* __restrict__ alpha,
                    float* __restrict__ ctx) {
    __shared__ float  sal[N_];
    __shared__ float4 sred[512];
    const int b  = blockIdx.x;
    const int d0 = blockIdx.y * 128;
    const int t  = threadIdx.x;
    for (int n = t; n < N_; n += 512) sal[n] = alpha[(size_t)b * N_ + n];
    __syncthreads();

    const int dl = (t & 31) * 4;
    const int nl = t >> 5;                       // 16 n-lanes
    const float* base = enc + (size_t)b * N_ * D_ + d0 + dl;
    float4 a0 = make_float4(0,0,0,0), a1 = a0, a2 = a0, a3 = a0;
    #pragma unroll 2
    for (int n = nl; n < N_; n += 64) {
        float s0 = sal[n], s1 = sal[n+16], s2 = sal[n+32], s3 = sal[n+48];
        float4 e0 = *(const float4*)(base + (size_t)(n     ) * D_);
        float4 e1 = *(const float4*)(base + (size_t)(n + 16) * D_);
        float4 e2 = *(const float4*)(base + (size_t)(n + 32) * D_);
        float4 e3 = *(const float4*)(base + (size_t)(n + 48) * D_);
        a0.x += s0*e0.x; a0.y += s0*e0.y; a0.z += s0*e0.z; a0.w += s0*e0.w;
        a1.x += s1*e1.x; a1.y += s1*e1.y; a1.z += s1*e1.z; a1.w += s1*e1.w;
        a2.x += s2*e2.x; a2.y += s2*e2.y; a2.z += s2*e2.z; a2.w += s2*e2.w;
        a3.x += s3*e3.x; a3.y += s3*e3.y; a3.z += s3*e3.z; a3.w += s3*e3.w;
    }
    a0.x += a1.x + a2.x + a3.x; a0.y += a1.y + a2.y + a3.y;
    a0.z += a1.z + a2.z + a3.z; a0.w += a1.w + a2.w + a3.w;
    sred[t] = a0;
    __syncthreads();
    if (t < 32) {
        float4 r = sred[t];
        #pragma unroll
        for (int j = 1; j < 16; j++) {
            float4 o = sred[t + 32 * j];
            r.x += o.x; r.y += o.y; r.z += o.z; r.w += o.w;
        }
        *(float4*)(ctx + (size_t)b * D_ + d0 + t * 4) = r;
    }
}

// ---------------------------------------------------------------------------
extern "C" void kernel_launch(void* const* d_in, const int* in_sizes, int n_in,
                              void* d_out, int out_size) {
    const float* h    = (const float*)d_in[0];
    const float* enc  = (const float*)d_in[1];
    const int*   mask = (const int*)  d_in[2];
    const float* Wh   = (const float*)d_in[3];
    const float* We   = (const float*)d_in[4];
    const float* v    = (const float*)d_in[5];

    float* out   = (float*)d_out;
    float* ctx   = out;               // (B, D) first
    float* alpha = out + B_ * D_;     // (B, N) second

    cudaFuncSetAttribute(scores_kernel, cudaFuncAttributeMaxDynamicSharedMemorySize, SMEM_BYTES);

    econv_kernel  <<<(M_ * (D_ / 4)) / 256, 256>>>(enc);
    proj_h_kernel <<<(B_ * A_) / 8, 256>>>(h, Wh);
    wsplit_kernel <<<512, 512>>>(We);
    scores_kernel <<<M_ / 128, 512, SMEM_BYTES>>>(v);
    softmax_kernel<<<B_, 256>>>(mask, alpha);
    context_kernel<<<dim3(B_, 4), 512>>>(enc, alpha, ctx);
}

// round 6
// speedup vs baseline: 2.3412x; 1.4361x over previous
#include <cuda_runtime.h>
#include <cuda_fp16.h>
#include <cstdint>

#define B_ 64
#define N_ 2048
#define H_ 512
#define D_ 512
#define A_ 512
#define M_ (B_*N_)
#define NEG_INF_ -1.0e9f

// ---------------- persistent device scratch ----------------
__device__ float g_proj_h[B_*A_];
__device__ float g_scores[M_];
__device__ __align__(16) __half g_We_h[A_*D_];
__device__ __align__(16) __half g_enc_h[(size_t)M_*D_];   // 128 MB

__device__ __forceinline__ uint32_t smem_u32(const void* p) {
    uint32_t a;
    asm("{ .reg .u64 t; cvta.to.shared.u64 t, %1; cvt.u32.u64 %0, t; }" : "=r"(a) : "l"(p));
    return a;
}

#define LDSM_X4(r, addr)                                                          \
    asm volatile("ldmatrix.sync.aligned.m8n8.x4.shared.b16 {%0,%1,%2,%3}, [%4];"  \
        : "=r"((r)[0]), "=r"((r)[1]), "=r"((r)[2]), "=r"((r)[3]) : "r"(addr))

#define MMA_F16(d, a, b0, b1)                                                     \
    asm volatile("mma.sync.aligned.m16n8k16.row.col.f32.f16.f16.f32 "             \
        "{%0,%1,%2,%3}, {%4,%5,%6,%7}, {%8,%9}, {%0,%1,%2,%3};"                   \
        : "+f"((d)[0]), "+f"((d)[1]), "+f"((d)[2]), "+f"((d)[3])                  \
        : "r"((a)[0]), "r"((a)[1]), "r"((a)[2]), "r"((a)[3]), "r"(b0), "r"(b1))

#define CP16(dst, src)  asm volatile("cp.async.cg.shared.global [%0], [%1], 16;" :: "r"(dst), "l"(src))
#define CP_COMMIT()     asm volatile("cp.async.commit_group;" ::: "memory")
#define CP_WAIT1()      asm volatile("cp.async.wait_group 1;" ::: "memory")
#define CP_WAIT0()      asm volatile("cp.async.wait_group 0;" ::: "memory")

// smem: 3 stages {E 128x64 fp16 (128B rows, SW128 xor), W 256x64 fp16}
#define STG     49152
#define OFF_E   0
#define OFF_W   16384
#define OFF_VS  (3*STG)
#define OFF_PS  (OFF_VS + 2048)
#define OFF_RED (OFF_PS + 2048)
#define SMEM_BYTES (OFF_RED + 2048)

// ---------------------------------------------------------------------------
__global__ void proj_h_kernel(const float* __restrict__ h,
                              const float* __restrict__ Wh) {
    int gw   = blockIdx.x * 8 + (threadIdx.x >> 5);
    int lane = threadIdx.x & 31;
    int b = gw / A_, a = gw % A_;
    const float* hr = h  + (size_t)b * H_;
    const float* wr = Wh + (size_t)a * H_;
    float s = 0.f;
    #pragma unroll 4
    for (int k = lane; k < H_; k += 32) s += hr[k] * wr[k];
    #pragma unroll
    for (int o = 16; o > 0; o >>= 1) s += __shfl_xor_sync(0xffffffffu, s, o);
    if (lane == 0) g_proj_h[(size_t)b * A_ + a] = s;
}

__global__ void wconv_kernel(const float* __restrict__ We) {
    int i = blockIdx.x * blockDim.x + threadIdx.x;
    g_We_h[i] = __float2half_rn(We[i]);
}

// enc -> fp16 (DRAM-bound one-shot: 256MB read, 128MB write)
__global__ void econv_kernel(const float* __restrict__ enc) {
    size_t i = ((size_t)blockIdx.x * blockDim.x + threadIdx.x) * 4;
    float4 e = *(const float4*)(enc + i);
    uint32_t p01, p23;
    asm("cvt.rn.f16x2.f32 %0, %1, %2;" : "=r"(p01) : "f"(e.y), "f"(e.x));
    asm("cvt.rn.f16x2.f32 %0, %1, %2;" : "=r"(p23) : "f"(e.w), "f"(e.z));
    *(uint2*)(g_enc_h + i) = make_uint2(p01, p23);
}

// ---------------------------------------------------------------------------
// scores: single-pass fp16 HMMA, 3-stage cp.async, SW128-swizzled smem,
// K-chunks of 64, fused tanh/v epilogue. 16 iters = 2 a-chunks x 8 K-chunks.
// ---------------------------------------------------------------------------
__global__ __launch_bounds__(512, 1)
void scores_kernel(const float* __restrict__ v) {
    extern __shared__ char smem[];
    const uint32_t sb = smem_u32(smem);
    const int tid  = threadIdx.x;
    const int lane = tid & 31;
    const int w    = tid >> 5;
    const int wm   = w & 3;            // 32-row band
    const int wn   = w >> 2;           // 64-col band
    const int m0   = blockIdx.x * 128;
    const int b    = blockIdx.x >> 4;

    float* vs = (float*)(smem + OFF_VS);
    float* ps = (float*)(smem + OFF_PS);
    vs[tid] = v[tid];
    ps[tid] = g_proj_h[(size_t)b * A_ + tid];

    // ldmatrix lane geometry (SW128: 16B segment XOR (row&7)*16)
    const uint32_t xr = (uint32_t)(lane & 7) * 16;
    const uint32_t eBase = OFF_E + (uint32_t)(wm * 32 + (lane & 15)) * 128;
    const uint32_t eT = (uint32_t)(lane >> 4) * 16;
    const int q = lane >> 3;
    const uint32_t wBase = OFF_W + (uint32_t)(wn * 64 + ((q >> 1) << 3) + (lane & 7)) * 128;
    const uint32_t wT = (uint32_t)(q & 1) * 16;

    float c[2][8][4];
    float sp[4] = {0.f, 0.f, 0.f, 0.f};
    #pragma unroll
    for (int i = 0; i < 2; i++)
        #pragma unroll
        for (int j = 0; j < 8; j++)
            #pragma unroll
            for (int e = 0; e < 4; e++) c[i][j][e] = 0.f;

    auto issue = [&](int ci) {
        const int ac = ci >> 3;
        const int k0 = (ci & 7) * 64;
        const uint32_t st = sb + (uint32_t)(ci % 3) * STG;
        #pragma unroll
        for (int i = 0; i < 2; i++) {                 // E: 1024 16B segs
            int idx = tid + i * 512, row = idx >> 3, seg = idx & 7;
            uint32_t sw = (uint32_t)row * 128 + (((uint32_t)seg * 16) ^ (((uint32_t)row & 7) * 16));
            CP16(st + OFF_E + sw, (const char*)(g_enc_h + (size_t)(m0 + row) * D_ + k0 + seg * 8));
        }
        #pragma unroll
        for (int i = 0; i < 4; i++) {                 // W: 2048 segs
            int idx = tid + i * 512, row = idx >> 3, seg = idx & 7;
            uint32_t sw = (uint32_t)row * 128 + (((uint32_t)seg * 16) ^ (((uint32_t)row & 7) * 16));
            CP16(st + OFF_W + sw, (const char*)(g_We_h + (size_t)(ac * 256 + row) * D_ + k0 + seg * 8));
        }
    };

    issue(0); CP_COMMIT();
    issue(1); CP_COMMIT();

    #pragma unroll 1
    for (int ci = 0; ci < 16; ci++) {
        if (ci < 15) { CP_WAIT1(); } else { CP_WAIT0(); }
        __syncthreads();
        if (ci + 2 < 16) { issue(ci + 2); CP_COMMIT(); }

        const uint32_t stb = sb + (uint32_t)(ci % 3) * STG;
        #pragma unroll
        for (int s = 0; s < 4; s++) {
            uint32_t aF[2][4];
            #pragma unroll
            for (int i = 0; i < 2; i++)
                LDSM_X4(aF[i], stb + eBase + (uint32_t)i * 2048 + (((uint32_t)s * 32 + eT) ^ xr));
            #pragma unroll
            for (int g = 0; g < 4; g++) {
                uint32_t bF[4];
                LDSM_X4(bF, stb + wBase + (uint32_t)g * 2048 + (((uint32_t)s * 32 + wT) ^ xr));
                #pragma unroll
                for (int i = 0; i < 2; i++) {
                    MMA_F16(c[i][2*g],   aF[i], bF[0], bF[1]);
                    MMA_F16(c[i][2*g+1], aF[i], bF[2], bF[3]);
                }
            }
        }

        if ((ci & 7) == 7) {        // end of a-chunk: fused tanh/v epilogue
            const int a0 = (ci >> 3) * 256;
            #pragma unroll
            for (int i = 0; i < 2; i++)
                #pragma unroll
                for (int j = 0; j < 8; j++)
                    #pragma unroll
                    for (int e = 0; e < 4; e++) {
                        int col = a0 + wn * 64 + j * 8 + (lane & 3) * 2 + (e & 1);
                        float x  = ps[col] + c[i][j][e];
                        float ex = __expf(2.f * x);
                        float th = 1.f - __fdividef(2.f, ex + 1.f);
                        sp[i * 2 + (e >> 1)] += vs[col] * th;
                        c[i][j][e] = 0.f;
                    }
        }
    }

    #pragma unroll
    for (int slot = 0; slot < 4; slot++) {
        sp[slot] += __shfl_xor_sync(0xffffffffu, sp[slot], 1);
        sp[slot] += __shfl_xor_sync(0xffffffffu, sp[slot], 2);
    }
    float* red = (float*)(smem + OFF_RED);
    __syncthreads();
    if ((lane & 3) == 0) {
        #pragma unroll
        for (int slot = 0; slot < 4; slot++) {
            int row = wm * 32 + (slot >> 1) * 16 + (slot & 1) * 8 + (lane >> 2);
            red[row * 4 + wn] = sp[slot];
        }
    }
    __syncthreads();
    if (tid < 128)
        g_scores[m0 + tid] = red[tid*4+0] + red[tid*4+1] + red[tid*4+2] + red[tid*4+3];
}

// ---------------------------------------------------------------------------
__global__ void softmax_kernel(const int* __restrict__ mask,
                               float* __restrict__ alpha) {
    __shared__ float sred[256];
    const int b   = blockIdx.x;
    const int tid = threadIdx.x;
    const float* sc = g_scores + (size_t)b * N_;
    const int*   mk = mask     + (size_t)b * N_;

    float vals[8];
    float mx = -3.4e38f;
    #pragma unroll
    for (int i = 0; i < 8; i++) {
        int n = tid + i * 256;
        float s = (mk[n] == 0) ? NEG_INF_ : sc[n];
        vals[i] = s;
        mx = fmaxf(mx, s);
    }
    sred[tid] = mx;
    __syncthreads();
    #pragma unroll
    for (int o = 128; o > 0; o >>= 1) {
        if (tid < o) sred[tid] = fmaxf(sred[tid], sred[tid + o]);
        __syncthreads();
    }
    mx = sred[0];
    __syncthreads();

    float sum = 0.f;
    #pragma unroll
    for (int i = 0; i < 8; i++) { vals[i] = expf(vals[i] - mx); sum += vals[i]; }
    sred[tid] = sum;
    __syncthreads();
    #pragma unroll
    for (int o = 128; o > 0; o >>= 1) {
        if (tid < o) sred[tid] += sred[tid + o];
        __syncthreads();
    }
    float inv = 1.f / sred[0];
    #pragma unroll
    for (int i = 0; i < 8; i++)
        alpha[(size_t)b * N_ + tid + i * 256] = vals[i] * inv;
}

// ---------------------------------------------------------------------------
// context[b,d] = sum_n alpha[b,n]*enc_h[b,n,d]  (fp16 loads, fp32 math)
// 512 threads, 16 d-groups of 8 halves, 32 n-lanes, 4 streams (MLP 4).
// ---------------------------------------------------------------------------
__global__ __launch_bounds__(512)
void context_kernel(const float* __restrict__ alpha,
                    float* __restrict__ ctx) {
    __shared__ float sal[N_];
    __shared__ float part[512 * 8];
    const int b  = blockIdx.x;
    const int d0 = blockIdx.y * 128;
    const int t  = threadIdx.x;
    for (int n = t; n < N_; n += 512) sal[n] = alpha[(size_t)b * N_ + n];
    __syncthreads();

    const int dg = t & 15;               // d-group: 8 halves
    const int nl = t >> 4;               // 32 n-lanes
    const __half* base = g_enc_h + (size_t)b * N_ * D_ + d0 + dg * 8;

    float acc[8];
    #pragma unroll
    for (int j = 0; j < 8; j++) acc[j] = 0.f;

    #pragma unroll 1
    for (int n = nl; n < N_; n += 128) {
        #pragma unroll
        for (int s = 0; s < 4; s++) {
            int nn = n + s * 32;
            float a = sal[nn];
            uint4 pk = *(const uint4*)(base + (size_t)nn * D_);
            float2 f0 = __half22float2(*(const __half2*)&pk.x);
            float2 f1 = __half22float2(*(const __half2*)&pk.y);
            float2 f2 = __half22float2(*(const __half2*)&pk.z);
            float2 f3 = __half22float2(*(const __half2*)&pk.w);
            acc[0] += a * f0.x; acc[1] += a * f0.y;
            acc[2] += a * f1.x; acc[3] += a * f1.y;
            acc[4] += a * f2.x; acc[5] += a * f2.y;
            acc[6] += a * f3.x; acc[7] += a * f3.y;
        }
    }
    #pragma unroll
    for (int j = 0; j < 8; j++) part[t * 8 + j] = acc[j];
    __syncthreads();
    if (t < 128) {
        int g = t >> 3, j = t & 7;
        float s = 0.f;
        #pragma unroll
        for (int m = 0; m < 32; m++) s += part[(g + 16 * m) * 8 + j];
        ctx[(size_t)b * D_ + d0 + g * 8 + j] = s;
    }
}

// ---------------------------------------------------------------------------
extern "C" void kernel_launch(void* const* d_in, const int* in_sizes, int n_in,
                              void* d_out, int out_size) {
    const float* h    = (const float*)d_in[0];
    const float* enc  = (const float*)d_in[1];
    const int*   mask = (const int*)  d_in[2];
    const float* Wh   = (const float*)d_in[3];
    const float* We   = (const float*)d_in[4];
    const float* v    = (const float*)d_in[5];

    float* out   = (float*)d_out;
    float* ctx   = out;               // (B, D) first
    float* alpha = out + B_ * D_;     // (B, N) second

    cudaFuncSetAttribute(scores_kernel, cudaFuncAttributeMaxDynamicSharedMemorySize, SMEM_BYTES);

    econv_kernel  <<<(M_ * (D_ / 4)) / 256, 256>>>(enc);
    proj_h_kernel <<<(B_ * A_) / 8, 256>>>(h, Wh);
    wconv_kernel  <<<512, 512>>>(We);
    scores_kernel <<<M_ / 128, 512, SMEM_BYTES>>>(v);
    softmax_kernel<<<B_, 256>>>(mask, alpha);
    context_kernel<<<dim3(B_, 4), 512>>>(alpha, ctx);
}

// round 7
// speedup vs baseline: 2.4888x; 1.0630x over previous
#include <cuda_runtime.h>
#include <cuda_fp16.h>
#include <cstdint>

#define B_ 64
#define N_ 2048
#define H_ 512
#define D_ 512
#define A_ 512
#define M_ (B_*N_)
#define NEG_INF_ -1.0e9f

// ---------------- persistent device scratch ----------------
__device__ float g_proj_h[B_*A_];
__device__ float g_scores[M_];
__device__ __align__(16) __half g_We_h[A_*D_];
__device__ __align__(16) __half g_enc_h[(size_t)M_*D_];   // 128 MB

__device__ __forceinline__ uint32_t smem_u32(const void* p) {
    uint32_t a;
    asm("{ .reg .u64 t; cvta.to.shared.u64 t, %1; cvt.u32.u64 %0, t; }" : "=r"(a) : "l"(p));
    return a;
}

#define LDSM_X4(r, addr)                                                          \
    asm volatile("ldmatrix.sync.aligned.m8n8.x4.shared.b16 {%0,%1,%2,%3}, [%4];"  \
        : "=r"((r)[0]), "=r"((r)[1]), "=r"((r)[2]), "=r"((r)[3]) : "r"(addr))

#define MMA_F16(d, a, b0, b1)                                                     \
    asm volatile("mma.sync.aligned.m16n8k16.row.col.f32.f16.f16.f32 "             \
        "{%0,%1,%2,%3}, {%4,%5,%6,%7}, {%8,%9}, {%0,%1,%2,%3};"                   \
        : "+f"((d)[0]), "+f"((d)[1]), "+f"((d)[2]), "+f"((d)[3])                  \
        : "r"((a)[0]), "r"((a)[1]), "r"((a)[2]), "r"((a)[3]), "r"(b0), "r"(b1))

#define CP16(dst, src)  asm volatile("cp.async.cg.shared.global [%0], [%1], 16;" :: "r"(dst), "l"(src))
#define CP_COMMIT()     asm volatile("cp.async.commit_group;" ::: "memory")
#define CP_WAIT1()      asm volatile("cp.async.wait_group 1;" ::: "memory")
#define CP_WAIT0()      asm volatile("cp.async.wait_group 0;" ::: "memory")

// smem: 2 stages {E 128x128 fp16 (256B rows, XOR swizzle), W 256x128 fp16}
#define STG     98304
#define OFF_E   0
#define OFF_W   32768
#define OFF_VS  (2*STG)
#define OFF_PS  (OFF_VS + 2048)
#define OFF_RED (OFF_PS + 2048)
#define SMEM_BYTES (OFF_RED + 2048)

// ---------------------------------------------------------------------------
__global__ void proj_h_kernel(const float* __restrict__ h,
                              const float* __restrict__ Wh) {
    int gw   = blockIdx.x * 8 + (threadIdx.x >> 5);
    int lane = threadIdx.x & 31;
    int b = gw / A_, a = gw % A_;
    const float* hr = h  + (size_t)b * H_;
    const float* wr = Wh + (size_t)a * H_;
    float s = 0.f;
    #pragma unroll 4
    for (int k = lane; k < H_; k += 32) s += hr[k] * wr[k];
    #pragma unroll
    for (int o = 16; o > 0; o >>= 1) s += __shfl_xor_sync(0xffffffffu, s, o);
    if (lane == 0) g_proj_h[(size_t)b * A_ + a] = s;
}

__global__ void wconv_kernel(const float* __restrict__ We) {
    int i = blockIdx.x * blockDim.x + threadIdx.x;
    g_We_h[i] = __float2half_rn(We[i]);
}

// enc -> fp16 (DRAM-bound one-shot)
__global__ void econv_kernel(const float* __restrict__ enc) {
    size_t i = ((size_t)blockIdx.x * blockDim.x + threadIdx.x) * 4;
    float4 e = *(const float4*)(enc + i);
    uint32_t p01, p23;
    asm("cvt.rn.f16x2.f32 %0, %1, %2;" : "=r"(p01) : "f"(e.y), "f"(e.x));
    asm("cvt.rn.f16x2.f32 %0, %1, %2;" : "=r"(p23) : "f"(e.w), "f"(e.z));
    *(uint2*)(g_enc_h + i) = make_uint2(p01, p23);
}

// ---------------------------------------------------------------------------
// scores: single-pass fp16 HMMA, 2-stage cp.async, K-chunks of 128,
// fused tanh.approx/v epilogue. 8 iters = 2 a-chunks x 4 K-chunks.
// ---------------------------------------------------------------------------
__global__ __launch_bounds__(512, 1)
void scores_kernel(const float* __restrict__ v) {
    extern __shared__ char smem[];
    const uint32_t sb = smem_u32(smem);
    const int tid  = threadIdx.x;
    const int lane = tid & 31;
    const int w    = tid >> 5;
    const int wm   = w & 3;            // 32-row band
    const int wn   = w >> 2;           // 64-col band
    const int m0   = blockIdx.x * 128;
    const int b    = blockIdx.x >> 4;

    float* vs = (float*)(smem + OFF_VS);
    float* ps = (float*)(smem + OFF_PS);
    vs[tid] = v[tid];
    ps[tid] = g_proj_h[(size_t)b * A_ + tid];

    // ldmatrix lane geometry; rows are 256B, XOR swizzle over 16B segs (atom=128B)
    const uint32_t xr = (uint32_t)(lane & 7) * 16;
    const uint32_t eBase = OFF_E + (uint32_t)(wm * 32 + (lane & 15)) * 256;
    const uint32_t eT = (uint32_t)(lane >> 4) * 16;
    const int q = lane >> 3;
    const uint32_t wBase = OFF_W + (uint32_t)(wn * 64 + ((q >> 1) << 3) + (lane & 7)) * 256;
    const uint32_t wT = (uint32_t)(q & 1) * 16;

    float c[2][8][4];
    float sp[4] = {0.f, 0.f, 0.f, 0.f};
    #pragma unroll
    for (int i = 0; i < 2; i++)
        #pragma unroll
        for (int j = 0; j < 8; j++)
            #pragma unroll
            for (int e = 0; e < 4; e++) c[i][j][e] = 0.f;

    auto issue = [&](int ci) {
        const int ac = ci >> 2;
        const int k0 = (ci & 3) * 128;
        const uint32_t st = sb + (uint32_t)(ci & 1) * STG;
        #pragma unroll
        for (int i = 0; i < 4; i++) {                 // E: 2048 16B segs
            int idx = tid + i * 512, row = idx >> 4, seg = idx & 15;
            uint32_t sw = (uint32_t)row * 256 + (((uint32_t)seg * 16) ^ (((uint32_t)row & 7) * 16));
            CP16(st + OFF_E + sw, (const char*)(g_enc_h + (size_t)(m0 + row) * D_ + k0 + seg * 8));
        }
        #pragma unroll
        for (int i = 0; i < 8; i++) {                 // W: 4096 segs
            int idx = tid + i * 512, row = idx >> 4, seg = idx & 15;
            uint32_t sw = (uint32_t)row * 256 + (((uint32_t)seg * 16) ^ (((uint32_t)row & 7) * 16));
            CP16(st + OFF_W + sw, (const char*)(g_We_h + (size_t)(ac * 256 + row) * D_ + k0 + seg * 8));
        }
    };

    issue(0); CP_COMMIT();

    #pragma unroll 1
    for (int ci = 0; ci < 8; ci++) {
        if (ci + 1 < 8) { issue(ci + 1); CP_COMMIT(); CP_WAIT1(); }
        else            { CP_WAIT0(); }
        __syncthreads();

        const uint32_t stb = sb + (uint32_t)(ci & 1) * STG;
        #pragma unroll
        for (int s = 0; s < 8; s++) {
            uint32_t aF[2][4];
            #pragma unroll
            for (int i = 0; i < 2; i++)
                LDSM_X4(aF[i], stb + eBase + (uint32_t)i * 4096 + (((uint32_t)s * 32 + eT) ^ xr));
            #pragma unroll
            for (int g = 0; g < 4; g++) {
                uint32_t bF[4];
                LDSM_X4(bF, stb + wBase + (uint32_t)g * 4096 + (((uint32_t)s * 32 + wT) ^ xr));
                #pragma unroll
                for (int i = 0; i < 2; i++) {
                    MMA_F16(c[i][2*g],   aF[i], bF[0], bF[1]);
                    MMA_F16(c[i][2*g+1], aF[i], bF[2], bF[3]);
                }
            }
        }
        __syncthreads();   // compute done before next issue overwrites this stage

        if ((ci & 3) == 3) {        // end of a-chunk: fused tanh/v epilogue
            const int a0 = (ci >> 2) * 256;
            #pragma unroll
            for (int i = 0; i < 2; i++)
                #pragma unroll
                for (int j = 0; j < 8; j++)
                    #pragma unroll
                    for (int e = 0; e < 4; e++) {
                        int col = a0 + wn * 64 + j * 8 + (lane & 3) * 2 + (e & 1);
                        float x  = ps[col] + c[i][j][e];
                        float th;
                        asm("tanh.approx.f32 %0, %1;" : "=f"(th) : "f"(x));
                        sp[i * 2 + (e >> 1)] += vs[col] * th;
                        c[i][j][e] = 0.f;
                    }
        }
    }

    #pragma unroll
    for (int slot = 0; slot < 4; slot++) {
        sp[slot] += __shfl_xor_sync(0xffffffffu, sp[slot], 1);
        sp[slot] += __shfl_xor_sync(0xffffffffu, sp[slot], 2);
    }
    float* red = (float*)(smem + OFF_RED);
    __syncthreads();
    if ((lane & 3) == 0) {
        #pragma unroll
        for (int slot = 0; slot < 4; slot++) {
            int row = wm * 32 + (slot >> 1) * 16 + (slot & 1) * 8 + (lane >> 2);
            red[row * 4 + wn] = sp[slot];
        }
    }
    __syncthreads();
    if (tid < 128)
        g_scores[m0 + tid] = red[tid*4+0] + red[tid*4+1] + red[tid*4+2] + red[tid*4+3];
}

// ---------------------------------------------------------------------------
__global__ void softmax_kernel(const int* __restrict__ mask,
                               float* __restrict__ alpha) {
    __shared__ float sred[256];
    const int b   = blockIdx.x;
    const int tid = threadIdx.x;
    const float* sc = g_scores + (size_t)b * N_;
    const int*   mk = mask     + (size_t)b * N_;

    float vals[8];
    float mx = -3.4e38f;
    #pragma unroll
    for (int i = 0; i < 8; i++) {
        int n = tid + i * 256;
        float s = (mk[n] == 0) ? NEG_INF_ : sc[n];
        vals[i] = s;
        mx = fmaxf(mx, s);
    }
    sred[tid] = mx;
    __syncthreads();
    #pragma unroll
    for (int o = 128; o > 0; o >>= 1) {
        if (tid < o) sred[tid] = fmaxf(sred[tid], sred[tid + o]);
        __syncthreads();
    }
    mx = sred[0];
    __syncthreads();

    float sum = 0.f;
    #pragma unroll
    for (int i = 0; i < 8; i++) { vals[i] = expf(vals[i] - mx); sum += vals[i]; }
    sred[tid] = sum;
    __syncthreads();
    #pragma unroll
    for (int o = 128; o > 0; o >>= 1) {
        if (tid < o) sred[tid] += sred[tid + o];
        __syncthreads();
    }
    float inv = 1.f / sred[0];
    #pragma unroll
    for (int i = 0; i < 8; i++)
        alpha[(size_t)b * N_ + tid + i * 256] = vals[i] * inv;
}

// ---------------------------------------------------------------------------
// context[b,d] = sum_n alpha[b,n]*enc_h[b,n,d]  (fp16 loads, fp32 math)
// ---------------------------------------------------------------------------
__global__ __launch_bounds__(512)
void context_kernel(const float* __restrict__ alpha,
                    float* __restrict__ ctx) {
    __shared__ float sal[N_];
    __shared__ float part[512 * 8];
    const int b  = blockIdx.x;
    const int d0 = blockIdx.y * 128;
    const int t  = threadIdx.x;
    for (int n = t; n < N_; n += 512) sal[n] = alpha[(size_t)b * N_ + n];
    __syncthreads();

    const int dg = t & 15;               // d-group: 8 halves
    const int nl = t >> 4;               // 32 n-lanes
    const __half* base = g_enc_h + (size_t)b * N_ * D_ + d0 + dg * 8;

    float acc[8];
    #pragma unroll
    for (int j = 0; j < 8; j++) acc[j] = 0.f;

    #pragma unroll 1
    for (int n = nl; n < N_; n += 128) {
        #pragma unroll
        for (int s = 0; s < 4; s++) {
            int nn = n + s * 32;
            float a = sal[nn];
            uint4 pk = *(const uint4*)(base + (size_t)nn * D_);
            float2 f0 = __half22float2(*(const __half2*)&pk.x);
            float2 f1 = __half22float2(*(const __half2*)&pk.y);
            float2 f2 = __half22float2(*(const __half2*)&pk.z);
            float2 f3 = __half22float2(*(const __half2*)&pk.w);
            acc[0] += a * f0.x; acc[1] += a * f0.y;
            acc[2] += a * f1.x; acc[3] += a * f1.y;
            acc[4] += a * f2.x; acc[5] += a * f2.y;
            acc[6] += a * f3.x; acc[7] += a * f3.y;
        }
    }
    #pragma unroll
    for (int j = 0; j < 8; j++) part[t * 8 + j] = acc[j];
    __syncthreads();
    if (t < 128) {
        int g = t >> 3, j = t & 7;
        float s = 0.f;
        #pragma unroll
        for (int m = 0; m < 32; m++) s += part[(g + 16 * m) * 8 + j];
        ctx[(size_t)b * D_ + d0 + g * 8 + j] = s;
    }
}

// ---------------------------------------------------------------------------
extern "C" void kernel_launch(void* const* d_in, const int* in_sizes, int n_in,
                              void* d_out, int out_size) {
    const float* h    = (const float*)d_in[0];
    const float* enc  = (const float*)d_in[1];
    const int*   mask = (const int*)  d_in[2];
    const float* Wh   = (const float*)d_in[3];
    const float* We   = (const float*)d_in[4];
    const float* v    = (const float*)d_in[5];

    float* out   = (float*)d_out;
    float* ctx   = out;               // (B, D) first
    float* alpha = out + B_ * D_;     // (B, N) second

    cudaFuncSetAttribute(scores_kernel, cudaFuncAttributeMaxDynamicSharedMemorySize, SMEM_BYTES);

    econv_kernel  <<<(M_ * (D_ / 4)) / 256, 256>>>(enc);
    proj_h_kernel <<<(B_ * A_) / 8, 256>>>(h, Wh);
    wconv_kernel  <<<512, 512>>>(We);
    scores_kernel <<<M_ / 128, 512, SMEM_BYTES>>>(v);
    softmax_kernel<<<B_, 256>>>(mask, alpha);
    context_kernel<<<dim3(B_, 4), 512>>>(alpha, ctx);
}

// round 8
// speedup vs baseline: 2.6215x; 1.0533x over previous
#include <cuda_runtime.h>
#include <cuda_fp16.h>
#include <cstdint>

#define B_ 64
#define N_ 2048
#define H_ 512
#define D_ 512
#define A_ 512
#define M_ (B_*N_)
#define NEG_INF_ -1.0e9f

// ---------------- persistent device scratch ----------------
__device__ float g_proj_h[B_*A_];
__device__ float g_scores[M_];
__device__ __align__(16) __half g_We_h[A_*D_];
__device__ __align__(16) __half g_enc_h[(size_t)M_*D_];   // 128 MB

__device__ __forceinline__ uint32_t smem_u32(const void* p) {
    uint32_t a;
    asm("{ .reg .u64 t; cvta.to.shared.u64 t, %1; cvt.u32.u64 %0, t; }" : "=r"(a) : "l"(p));
    return a;
}

#define LDSM_X4(r, addr)                                                          \
    asm volatile("ldmatrix.sync.aligned.m8n8.x4.shared.b16 {%0,%1,%2,%3}, [%4];"  \
        : "=r"((r)[0]), "=r"((r)[1]), "=r"((r)[2]), "=r"((r)[3]) : "r"(addr))

#define MMA_F16(d, a, b0, b1)                                                     \
    asm volatile("mma.sync.aligned.m16n8k16.row.col.f32.f16.f16.f32 "             \
        "{%0,%1,%2,%3}, {%4,%5,%6,%7}, {%8,%9}, {%0,%1,%2,%3};"                   \
        : "+f"((d)[0]), "+f"((d)[1]), "+f"((d)[2]), "+f"((d)[3])                  \
        : "r"((a)[0]), "r"((a)[1]), "r"((a)[2]), "r"((a)[3]), "r"(b0), "r"(b1))

#define CP16(dst, src)  asm volatile("cp.async.cg.shared.global [%0], [%1], 16;" :: "r"(dst), "l"(src))
#define CP_COMMIT()     asm volatile("cp.async.commit_group;" ::: "memory")
#define CP_WAIT1()      asm volatile("cp.async.wait_group 1;" ::: "memory")
#define CP_WAIT0()      asm volatile("cp.async.wait_group 0;" ::: "memory")

// smem: 2 stages {E 64x64 fp16 (128B rows, SW128 xor), W 256x64 fp16}
#define STG     40960
#define OFF_E   0
#define OFF_W   8192
#define OFF_VS  (2*STG)
#define OFF_PS  (OFF_VS + 2048)
#define OFF_RED (OFF_PS + 2048)
#define SMEM_BYTES (OFF_RED + 1024)

// ---------------------------------------------------------------------------
__global__ void proj_h_kernel(const float* __restrict__ h,
                              const float* __restrict__ Wh) {
    int gw   = blockIdx.x * 8 + (threadIdx.x >> 5);
    int lane = threadIdx.x & 31;
    int b = gw / A_, a = gw % A_;
    const float* hr = h  + (size_t)b * H_;
    const float* wr = Wh + (size_t)a * H_;
    float s = 0.f;
    #pragma unroll 4
    for (int k = lane; k < H_; k += 32) s += hr[k] * wr[k];
    #pragma unroll
    for (int o = 16; o > 0; o >>= 1) s += __shfl_xor_sync(0xffffffffu, s, o);
    if (lane == 0) g_proj_h[(size_t)b * A_ + a] = s;
}

__global__ void wconv_kernel(const float* __restrict__ We) {
    int i = blockIdx.x * blockDim.x + threadIdx.x;
    g_We_h[i] = __float2half_rn(We[i]);
}

// enc -> fp16 (DRAM-bound one-shot)
__global__ void econv_kernel(const float* __restrict__ enc) {
    size_t i = ((size_t)blockIdx.x * blockDim.x + threadIdx.x) * 4;
    float4 e = *(const float4*)(enc + i);
    uint32_t p01, p23;
    asm("cvt.rn.f16x2.f32 %0, %1, %2;" : "=r"(p01) : "f"(e.y), "f"(e.x));
    asm("cvt.rn.f16x2.f32 %0, %1, %2;" : "=r"(p23) : "f"(e.w), "f"(e.z));
    *(uint2*)(g_enc_h + i) = make_uint2(p01, p23);
}

// ---------------------------------------------------------------------------
// scores: single-pass fp16 HMMA. 256-thread CTA, M-tile 64, 2 CTAs/SM.
// 2-stage cp.async, K-chunks of 64; 16 iters = 2 a-chunks x 8 K-chunks.
// Fused tanh.approx/v epilogue.
// ---------------------------------------------------------------------------
__global__ __launch_bounds__(256, 2)
void scores_kernel(const float* __restrict__ v) {
    extern __shared__ char smem[];
    const uint32_t sb = smem_u32(smem);
    const int tid  = threadIdx.x;
    const int lane = tid & 31;
    const int w    = tid >> 5;
    const int wm   = w & 1;            // 2 x 32-row bands
    const int wn   = w >> 1;           // 4 x 64-col bands
    const int m0   = blockIdx.x * 64;
    const int b    = blockIdx.x >> 5;

    float* vs = (float*)(smem + OFF_VS);
    float* ps = (float*)(smem + OFF_PS);
    #pragma unroll
    for (int i = 0; i < 2; i++) {
        vs[tid + i * 256] = v[tid + i * 256];
        ps[tid + i * 256] = g_proj_h[(size_t)b * A_ + tid + i * 256];
    }

    // ldmatrix lane geometry (SW128: 16B segment XOR (row&7)*16; 128B rows)
    const uint32_t xr = (uint32_t)(lane & 7) * 16;
    const uint32_t eBase = OFF_E + (uint32_t)(wm * 32 + (lane & 15)) * 128;
    const uint32_t eT = (uint32_t)(lane >> 4) * 16;
    const int q = lane >> 3;
    const uint32_t wBase = OFF_W + (uint32_t)(wn * 64 + ((q >> 1) << 3) + (lane & 7)) * 128;
    const uint32_t wT = (uint32_t)(q & 1) * 16;

    float c[2][8][4];
    float sp[4] = {0.f, 0.f, 0.f, 0.f};
    #pragma unroll
    for (int i = 0; i < 2; i++)
        #pragma unroll
        for (int j = 0; j < 8; j++)
            #pragma unroll
            for (int e = 0; e < 4; e++) c[i][j][e] = 0.f;

    auto issue = [&](int ci) {
        const int ac = ci >> 3;
        const int k0 = (ci & 7) * 64;
        const uint32_t st = sb + (uint32_t)(ci & 1) * STG;
        #pragma unroll
        for (int i = 0; i < 2; i++) {                 // E: 512 16B segs
            int idx = tid + i * 256, row = idx >> 3, seg = idx & 7;
            uint32_t sw = (uint32_t)row * 128 + (((uint32_t)seg * 16) ^ (((uint32_t)row & 7) * 16));
            CP16(st + OFF_E + sw, (const char*)(g_enc_h + (size_t)(m0 + row) * D_ + k0 + seg * 8));
        }
        #pragma unroll
        for (int i = 0; i < 8; i++) {                 // W: 2048 segs
            int idx = tid + i * 256, row = idx >> 3, seg = idx & 7;
            uint32_t sw = (uint32_t)row * 128 + (((uint32_t)seg * 16) ^ (((uint32_t)row & 7) * 16));
            CP16(st + OFF_W + sw, (const char*)(g_We_h + (size_t)(ac * 256 + row) * D_ + k0 + seg * 8));
        }
    };

    issue(0); CP_COMMIT();

    #pragma unroll 1
    for (int ci = 0; ci < 16; ci++) {
        if (ci + 1 < 16) { issue(ci + 1); CP_COMMIT(); CP_WAIT1(); }
        else             { CP_WAIT0(); }
        __syncthreads();

        const uint32_t stb = sb + (uint32_t)(ci & 1) * STG;
        #pragma unroll
        for (int s = 0; s < 4; s++) {
            uint32_t aF[2][4];
            #pragma unroll
            for (int i = 0; i < 2; i++)
                LDSM_X4(aF[i], stb + eBase + (uint32_t)i * 2048 + (((uint32_t)s * 32 + eT) ^ xr));
            #pragma unroll
            for (int g = 0; g < 4; g++) {
                uint32_t bF[4];
                LDSM_X4(bF, stb + wBase + (uint32_t)g * 2048 + (((uint32_t)s * 32 + wT) ^ xr));
                #pragma unroll
                for (int i = 0; i < 2; i++) {
                    MMA_F16(c[i][2*g],   aF[i], bF[0], bF[1]);
                    MMA_F16(c[i][2*g+1], aF[i], bF[2], bF[3]);
                }
            }
        }
        __syncthreads();   // compute done before next issue overwrites this stage

        if ((ci & 7) == 7) {        // end of a-chunk: fused tanh/v epilogue
            const int a0 = (ci >> 3) * 256;
            #pragma unroll
            for (int i = 0; i < 2; i++)
                #pragma unroll
                for (int j = 0; j < 8; j++)
                    #pragma unroll
                    for (int e = 0; e < 4; e++) {
                        int col = a0 + wn * 64 + j * 8 + (lane & 3) * 2 + (e & 1);
                        float x  = ps[col] + c[i][j][e];
                        float th;
                        asm("tanh.approx.f32 %0, %1;" : "=f"(th) : "f"(x));
                        sp[i * 2 + (e >> 1)] += vs[col] * th;
                        c[i][j][e] = 0.f;
                    }
        }
    }

    #pragma unroll
    for (int slot = 0; slot < 4; slot++) {
        sp[slot] += __shfl_xor_sync(0xffffffffu, sp[slot], 1);
        sp[slot] += __shfl_xor_sync(0xffffffffu, sp[slot], 2);
    }
    float* red = (float*)(smem + OFF_RED);
    __syncthreads();
    if ((lane & 3) == 0) {
        #pragma unroll
        for (int slot = 0; slot < 4; slot++) {
            int row = wm * 32 + (slot >> 1) * 16 + (slot & 1) * 8 + (lane >> 2);
            red[row * 4 + wn] = sp[slot];
        }
    }
    __syncthreads();
    if (tid < 64)
        g_scores[m0 + tid] = red[tid*4+0] + red[tid*4+1] + red[tid*4+2] + red[tid*4+3];
}

// ---------------------------------------------------------------------------
__global__ void softmax_kernel(const int* __restrict__ mask,
                               float* __restrict__ alpha) {
    __shared__ float sred[256];
    const int b   = blockIdx.x;
    const int tid = threadIdx.x;
    const float* sc = g_scores + (size_t)b * N_;
    const int*   mk = mask     + (size_t)b * N_;

    float vals[8];
    float mx = -3.4e38f;
    #pragma unroll
    for (int i = 0; i < 8; i++) {
        int n = tid + i * 256;
        float s = (mk[n] == 0) ? NEG_INF_ : sc[n];
        vals[i] = s;
        mx = fmaxf(mx, s);
    }
    sred[tid] = mx;
    __syncthreads();
    #pragma unroll
    for (int o = 128; o > 0; o >>= 1) {
        if (tid < o) sred[tid] = fmaxf(sred[tid], sred[tid + o]);
        __syncthreads();
    }
    mx = sred[0];
    __syncthreads();

    float sum = 0.f;
    #pragma unroll
    for (int i = 0; i < 8; i++) { vals[i] = expf(vals[i] - mx); sum += vals[i]; }
    sred[tid] = sum;
    __syncthreads();
    #pragma unroll
    for (int o = 128; o > 0; o >>= 1) {
        if (tid < o) sred[tid] += sred[tid + o];
        __syncthreads();
    }
    float inv = 1.f / sred[0];
    #pragma unroll
    for (int i = 0; i < 8; i++)
        alpha[(size_t)b * N_ + tid + i * 256] = vals[i] * inv;
}

// ---------------------------------------------------------------------------
// context[b,d] = sum_n alpha[b,n]*enc_h[b,n,d]  (fp16 loads, fp32 math)
// ---------------------------------------------------------------------------
__global__ __launch_bounds__(512)
void context_kernel(const float* __restrict__ alpha,
                    float* __restrict__ ctx) {
    __shared__ float sal[N_];
    __shared__ float part[512 * 8];
    const int b  = blockIdx.x;
    const int d0 = blockIdx.y * 128;
    const int t  = threadIdx.x;
    for (int n = t; n < N_; n += 512) sal[n] = alpha[(size_t)b * N_ + n];
    __syncthreads();

    const int dg = t & 15;               // d-group: 8 halves
    const int nl = t >> 4;               // 32 n-lanes
    const __half* base = g_enc_h + (size_t)b * N_ * D_ + d0 + dg * 8;

    float acc[8];
    #pragma unroll
    for (int j = 0; j < 8; j++) acc[j] = 0.f;

    #pragma unroll 1
    for (int n = nl; n < N_; n += 128) {
        #pragma unroll
        for (int s = 0; s < 4; s++) {
            int nn = n + s * 32;
            float a = sal[nn];
            uint4 pk = *(const uint4*)(base + (size_t)nn * D_);
            float2 f0 = __half22float2(*(const __half2*)&pk.x);
            float2 f1 = __half22float2(*(const __half2*)&pk.y);
            float2 f2 = __half22float2(*(const __half2*)&pk.z);
            float2 f3 = __half22float2(*(const __half2*)&pk.w);
            acc[0] += a * f0.x; acc[1] += a * f0.y;
            acc[2] += a * f1.x; acc[3] += a * f1.y;
            acc[4] += a * f2.x; acc[5] += a * f2.y;
            acc[6] += a * f3.x; acc[7] += a * f3.y;
        }
    }
    #pragma unroll
    for (int j = 0; j < 8; j++) part[t * 8 + j] = acc[j];
    __syncthreads();
    if (t < 128) {
        int g = t >> 3, j = t & 7;
        float s = 0.f;
        #pragma unroll
        for (int m = 0; m < 32; m++) s += part[(g + 16 * m) * 8 + j];
        ctx[(size_t)b * D_ + d0 + g * 8 + j] = s;
    }
}

// ---------------------------------------------------------------------------
extern "C" void kernel_launch(void* const* d_in, const int* in_sizes, int n_in,
                              void* d_out, int out_size) {
    const float* h    = (const float*)d_in[0];
    const float* enc  = (const float*)d_in[1];
    const int*   mask = (const int*)  d_in[2];
    const float* Wh   = (const float*)d_in[3];
    const float* We   = (const float*)d_in[4];
    const float* v    = (const float*)d_in[5];

    float* out   = (float*)d_out;
    float* ctx   = out;               // (B, D) first
    float* alpha = out + B_ * D_;     // (B, N) second

    cudaFuncSetAttribute(scores_kernel, cudaFuncAttributeMaxDynamicSharedMemorySize, SMEM_BYTES);

    econv_kernel  <<<(M_ * (D_ / 4)) / 256, 256>>>(enc);
    proj_h_kernel <<<(B_ * A_) / 8, 256>>>(h, Wh);
    wconv_kernel  <<<512, 512>>>(We);
    scores_kernel <<<M_ / 64, 256, SMEM_BYTES>>>(v);
    softmax_kernel<<<B_, 256>>>(mask, alpha);
    context_kernel<<<dim3(B_, 4), 512>>>(alpha, ctx);
}